// round 3
// baseline (speedup 1.0000x reference)
#include <cuda_runtime.h>
#include <math.h>

#define BATCH 8
#define CH    512
#define NPIX  4096   // 64*64
#define TOTAL ((size_t)BATCH * CH * NPIX)   // 16,777,216 floats

// Scratch: energy sum S[b][i][j], later overwritten in-place with attention.
__device__ float g_S[(size_t)BATCH * CH * CH];   // 8 MiB

// ---------------------------------------------------------------------------
// K1: S[b,i,j] = sum_n Qr[b,i,n]*Qr[b,j,n] + Qd[b,i,n]*Qd[b,j,n]
// grid (CH/64, CH/64, BATCH), block 256. Early-exits when gamma == 0.
// ---------------------------------------------------------------------------
__global__ __launch_bounds__(256)
void k_energy(const float* __restrict__ xr,
              const float* __restrict__ xd,
              const float* __restrict__ gamma)
{
    if (gamma[0] == 0.0f) return;   // algebraic short-circuit

    const int b  = blockIdx.z;
    const int i0 = blockIdx.y * 64;
    const int j0 = blockIdx.x * 64;

    __shared__ float As[64][17];
    __shared__ float Bs[64][17];

    const int tid = threadIdx.x;
    const int tx  = tid & 15;       // 0..15
    const int ty  = tid >> 4;       // 0..15

    float acc[4][4];
    #pragma unroll
    for (int i = 0; i < 4; i++)
        #pragma unroll
        for (int j = 0; j < 4; j++) acc[i][j] = 0.0f;

    const int lrow = tid >> 2;          // 0..63
    const int lk   = (tid & 3) * 4;     // 0,4,8,12

    for (int src = 0; src < 2; src++) {
        const float* Q = (src == 0 ? xr : xd) + (size_t)b * CH * NPIX;
        for (int k0 = 0; k0 < NPIX; k0 += 16) {
            float4 va = *(const float4*)&Q[(size_t)(i0 + lrow) * NPIX + k0 + lk];
            As[lrow][lk]     = va.x; As[lrow][lk + 1] = va.y;
            As[lrow][lk + 2] = va.z; As[lrow][lk + 3] = va.w;
            float4 vb = *(const float4*)&Q[(size_t)(j0 + lrow) * NPIX + k0 + lk];
            Bs[lrow][lk]     = vb.x; Bs[lrow][lk + 1] = vb.y;
            Bs[lrow][lk + 2] = vb.z; Bs[lrow][lk + 3] = vb.w;
            __syncthreads();

            #pragma unroll
            for (int k = 0; k < 16; k++) {
                float a[4], bv[4];
                #pragma unroll
                for (int i = 0; i < 4; i++) a[i]  = As[ty * 4 + i][k];
                #pragma unroll
                for (int j = 0; j < 4; j++) bv[j] = Bs[tx * 4 + j][k];
                #pragma unroll
                for (int i = 0; i < 4; i++)
                    #pragma unroll
                    for (int j = 0; j < 4; j++)
                        acc[i][j] = fmaf(a[i], bv[j], acc[i][j]);
            }
            __syncthreads();
        }
    }

    #pragma unroll
    for (int i = 0; i < 4; i++) {
        const size_t row = (size_t)b * CH + i0 + ty * 4 + i;
        #pragma unroll
        for (int j = 0; j < 4; j++)
            g_S[row * CH + j0 + tx * 4 + j] = acc[i][j];
    }
}

// ---------------------------------------------------------------------------
// K2: attention = softmax(-S) row-wise, in place.
// (max-subtract terms of the reference are softmax shift-invariant.)
// grid (BATCH*CH), block 256, 2 elements per thread.
// ---------------------------------------------------------------------------
__global__ __launch_bounds__(256)
void k_softmax(const float* __restrict__ gamma)
{
    if (gamma[0] == 0.0f) return;

    float* s = g_S + (size_t)blockIdx.x * CH;
    const int tid = threadIdx.x;

    float v0 = -s[tid];
    float v1 = -s[tid + 256];

    __shared__ float red[256];

    // row max
    red[tid] = fmaxf(v0, v1);
    __syncthreads();
    for (int w = 128; w > 0; w >>= 1) {
        if (tid < w) red[tid] = fmaxf(red[tid], red[tid + w]);
        __syncthreads();
    }
    const float m = red[0];
    __syncthreads();

    const float e0 = expf(v0 - m);
    const float e1 = expf(v1 - m);

    // row sum
    red[tid] = e0 + e1;
    __syncthreads();
    for (int w = 128; w > 0; w >>= 1) {
        if (tid < w) red[tid] += red[tid + w];
        __syncthreads();
    }
    const float inv = 1.0f / red[0];

    s[tid]       = e0 * inv;
    s[tid + 256] = e1 * inv;
}

// ---------------------------------------------------------------------------
// K3: out = gamma * (A @ Qr) + x_rgb.
// When gamma == 0 this is exactly out = x_rgb (finite A@Qr): float4 copy,
// 4096 blocks x 256 threads x 4 float4s each = 16,777,216 floats exactly.
// grid (NPIX/64, CH/64, BATCH), block 256.
// ---------------------------------------------------------------------------
__global__ __launch_bounds__(256)
void k_out(const float* __restrict__ xr,
           const float* __restrict__ gamma,
           float* __restrict__ out)
{
    const float g = gamma[0];
    const int tid = threadIdx.x;

    if (g == 0.0f) {
        // Linearized block id over the 3D grid (4096 blocks total).
        const size_t bid = (size_t)blockIdx.x
                         + (size_t)blockIdx.y * gridDim.x
                         + (size_t)blockIdx.z * gridDim.x * gridDim.y;
        const float4* src = (const float4*)xr;
        float4*       dst = (float4*)out;
        // Each block copies a contiguous 4096-float4 span; each thread 4
        // independent float4s (MLP=4), coalesced within each iteration.
        const size_t base = bid * (256 * 4);
        float4 v0 = src[base + tid];
        float4 v1 = src[base + tid + 256];
        float4 v2 = src[base + tid + 512];
        float4 v3 = src[base + tid + 768];
        dst[base + tid]       = v0;
        dst[base + tid + 256] = v1;
        dst[base + tid + 512] = v2;
        dst[base + tid + 768] = v3;
        return;
    }

    const int b  = blockIdx.z;
    const int i0 = blockIdx.y * 64;
    const int n0 = blockIdx.x * 64;
    const size_t base = (size_t)b * CH * NPIX;

    // Full path: acc[i][n] = sum_d A[b,i,d] * Qr[b,d,n]
    __shared__ float As[64][17];   // attention tile: 64 rows x 16 d
    __shared__ float Bs[16][68];   // Qr tile:        16 d   x 64 n

    const int tx = tid & 15;
    const int ty = tid >> 4;

    float acc[4][4];
    #pragma unroll
    for (int i = 0; i < 4; i++)
        #pragma unroll
        for (int j = 0; j < 4; j++) acc[i][j] = 0.0f;

    const int arow = tid >> 2;          // 0..63
    const int adk  = (tid & 3) * 4;     // 0..12
    const int bdr  = tid >> 4;          // 0..15
    const int bnc  = (tid & 15) * 4;    // 0..60

    for (int k0 = 0; k0 < CH; k0 += 16) {
        float4 va = *(const float4*)&g_S[((size_t)b * CH + i0 + arow) * CH + k0 + adk];
        As[arow][adk]     = va.x; As[arow][adk + 1] = va.y;
        As[arow][adk + 2] = va.z; As[arow][adk + 3] = va.w;
        float4 vb = *(const float4*)&xr[base + (size_t)(k0 + bdr) * NPIX + n0 + bnc];
        Bs[bdr][bnc]     = vb.x; Bs[bdr][bnc + 1] = vb.y;
        Bs[bdr][bnc + 2] = vb.z; Bs[bdr][bnc + 3] = vb.w;
        __syncthreads();

        #pragma unroll
        for (int k = 0; k < 16; k++) {
            float a[4], bv[4];
            #pragma unroll
            for (int i = 0; i < 4; i++) a[i]  = As[ty * 4 + i][k];
            #pragma unroll
            for (int j = 0; j < 4; j++) bv[j] = Bs[k][tx * 4 + j];
            #pragma unroll
            for (int i = 0; i < 4; i++)
                #pragma unroll
                for (int j = 0; j < 4; j++)
                    acc[i][j] = fmaf(a[i], bv[j], acc[i][j]);
        }
        __syncthreads();
    }

    #pragma unroll
    for (int i = 0; i < 4; i++) {
        const size_t off = base + (size_t)(i0 + ty * 4 + i) * NPIX + n0 + tx * 4;
        float4 x = *(const float4*)&xr[off];
        float4 o;
        o.x = fmaf(g, acc[i][0], x.x);
        o.y = fmaf(g, acc[i][1], x.y);
        o.z = fmaf(g, acc[i][2], x.z);
        o.w = fmaf(g, acc[i][3], x.w);
        *(float4*)&out[off] = o;
    }
}

// ---------------------------------------------------------------------------
extern "C" void kernel_launch(void* const* d_in, const int* in_sizes, int n_in,
                              void* d_out, int out_size)
{
    const float* x_rgb = (const float*)d_in[0];
    const float* x_dep = (const float*)d_in[1];
    const float* gamma = (const float*)d_in[2];
    float* out = (float*)d_out;

    dim3 blk(256);
    dim3 g1(CH / 64, CH / 64, BATCH);      // 8 x 8 x 8
    dim3 g2(BATCH * CH);                   // 4096 rows
    dim3 g3(NPIX / 64, CH / 64, BATCH);    // 64 x 8 x 8

    k_energy<<<g1, blk>>>(x_rgb, x_dep, gamma);
    k_softmax<<<g2, blk>>>(gamma);
    k_out<<<g3, blk>>>(x_rgb, gamma, out);
}